// round 11
// baseline (speedup 1.0000x reference)
#include <cuda_runtime.h>
#include <cuda_fp16.h>
#include <mma.h>
#include <cstdint>
#include <cstddef>

using namespace nvcuda;

#define D   64
#define H   4
#define NEG 0.2f
#define BN_EPS 1e-5f

#define NMAX 50000
#define EMAX 800000

// ---------------- scratch (static device globals; no allocation) ----------------
__device__ __half  g_uh[(size_t)NMAX * 64];     // [N][64] fp16 post-PReLU features
__device__ __half  g_zh[(size_t)NMAX * 256];    // [N][h*64+k] fp16 aggregated u
__device__ __half  g_wgT[64 * 256];             // B[j][h*64+k] = Wgat[(h*64+j)*64+k]
__device__ float  g_asrc[NMAX * H];
__device__ float  g_adst[NMAX * H];
__device__ float  g_wcsr[(size_t)EMAX * H];     // per-edge weights (CSR order)
__device__ float  g_wself[NMAX * H];
__device__ float  g_cs[H * D];                  // W_gat_h^T att_src_h
__device__ float  g_cd[H * D];                  // W_gat_h^T att_dst_h
__device__ int    g_cnt[NMAX];
__device__ int    g_rowptr[NMAX + 1];
__device__ int    g_cursor[NMAX];
__device__ int    g_csrc[EMAX];
__device__ int    g_spref[256];                 // chained-scan block prefixes
__device__ int    g_sflag[256];                 // chained-scan ready flags
__device__ int    g_ticket;                     // chained-scan block ticket
__device__ int    g_bncnt;                      // bnstats last-block counter
__device__ double g_sums[128];                  // [0:64) sum, [64:128) sumsq
__device__ float  g_bnsc[64], g_bnsh[64];

// ---------------- fast exp: FMA polynomial (no MUFU) ----------------
__device__ __forceinline__ float fexp(float x) {
    x = fmaxf(x, -80.f);
    float y  = x * 1.44269504089f;
    float t  = y + 12582912.0f;
    int   ki = __float_as_int(t) - 0x4B400000;
    float r  = y - (t - 12582912.0f);
    float p  = 1.5403530e-4f;
    p = fmaf(p, r, 1.3333558e-3f);
    p = fmaf(p, r, 9.6181291e-3f);
    p = fmaf(p, r, 5.5504109e-2f);
    p = fmaf(p, r, 2.4022651e-1f);
    p = fmaf(p, r, 6.9314718e-1f);
    p = fmaf(p, r, 1.0f);
    return __int_as_float(__float_as_int(p) + (ki << 23));
}

__device__ __forceinline__ float lrelu(float v) { return (v >= 0.f) ? v : NEG * v; }

// ============================================================================
// K_init: zero counters/flags/sums; block 0 builds c_src/c_dst + fp16 B matrix
// ============================================================================
__global__ void k_init(const float* __restrict__ Wgat,
                       const float* __restrict__ attS,
                       const float* __restrict__ attD, int n) {
    int gid = blockIdx.x * blockDim.x + threadIdx.x;
    int stride = gridDim.x * blockDim.x;
    for (int i = gid; i < n; i += stride) g_cnt[i] = 0;
    if (blockIdx.x == 0) {
        int tid = threadIdx.x;
        if (tid < 128) g_sums[tid] = 0.0;
        if (tid < 256) { g_sflag[tid] = 0; g_spref[tid] = 0; }
        if (tid == 0) { g_ticket = 0; g_bncnt = 0; }
        {
            int h = tid >> 6, k = tid & 63;
            float s = 0.f, d2 = 0.f;
            #pragma unroll 8
            for (int dd = 0; dd < 64; dd++) {
                float wv = Wgat[(h * 64 + dd) * 64 + k];
                s  += attS[h * 64 + dd] * wv;
                d2 += attD[h * 64 + dd] * wv;
            }
            g_cs[tid] = s;
            g_cd[tid] = d2;
        }
        for (int i = tid; i < 64 * 256; i += 256) {
            int j = i >> 8, c = i & 255;
            int h = c >> 6, k = c & 63;
            g_wgT[j * 256 + c] = __float2half_rn(Wgat[(h * 64 + j) * 64 + k]);
        }
    }
}

// ============================================================================
// K_A: u = PReLU(x W_lin^T + b) -> g_uh (fp16);  a_src/a_dst dots;  histogram.
// ============================================================================
#define KA_FLOATS (4608 + 4608 + 2*68*4 + 2304)
#define KA_SMEM   (KA_FLOATS * 4)

__global__ __launch_bounds__(256) void k_ulinear(
    const float* __restrict__ x, const float* __restrict__ Wlin,
    const float* __restrict__ blin, const float* __restrict__ pw,
    const int* __restrict__ dstA, int nrows, int nedges)
{
    extern __shared__ float sm[];
    float*  sX  = sm;                        // [64][72] x tile; later aliased by sU
    float*  sU  = sm;                        // [col][row] u fp32 (alias of sX)
    float*  sW  = sm + 4608;                 // [64][72] Wlin^T
    float*  sC  = sm + 9216;                 // [4][68]
    float*  sC2 = sm + 9216 + 272;           // [4][68]
    __half* sUh = (__half*)(sm + 9760);      // [row][72] u fp16
    const int tid  = threadIdx.x;
    const int row0 = blockIdx.x * 64;

    // destination histogram (independent, overlaps)
    {
        int gid = blockIdx.x * 256 + tid;
        int stride = gridDim.x * 256;
        for (int i = gid; i < nedges; i += stride)
            atomicAdd(&g_cnt[dstA[i]], 1);
    }

    {
        int h = tid >> 6, k = tid & 63;
        sC [h * 68 + k] = g_cs[tid];
        sC2[h * 68 + k] = g_cd[tid];
    }
    for (int i = tid; i < 64 * 64; i += 256) {
        int r = i >> 6, k = i & 63;
        int gr = row0 + r;
        sX[k * 72 + r] = (gr < nrows) ? x[(size_t)gr * D + k] : 0.f;
    }
    for (int i = tid; i < 64 * 64; i += 256) {
        int j = i >> 6, k = i & 63;
        sW[k * 72 + j] = Wlin[i];
    }
    __syncthreads();

    float accv[4][4];
    {
        const int rg = (tid >> 4) << 2;
        const int cg = (tid & 15) << 2;
        #pragma unroll
        for (int a = 0; a < 4; a++)
            #pragma unroll
            for (int b = 0; b < 4; b++) accv[a][b] = 0.f;
        #pragma unroll 8
        for (int k = 0; k < 64; k++) {
            float4 a4 = *(const float4*)(sX + k * 72 + rg);
            float4 b4 = *(const float4*)(sW + k * 72 + cg);
            float av[4] = {a4.x, a4.y, a4.z, a4.w};
            float bv[4] = {b4.x, b4.y, b4.z, b4.w};
            #pragma unroll
            for (int ri = 0; ri < 4; ri++)
                #pragma unroll
                for (int cj = 0; cj < 4; cj++) accv[ri][cj] += av[ri] * bv[cj];
        }
    }
    __syncthreads();   // all reads of sX done; safe to alias with sU

    {
        const int rg = (tid >> 4) << 2;
        const int cg = (tid & 15) << 2;
        float4 bb = *(const float4*)(blin + cg);
        float4 pp = *(const float4*)(pw + cg);
        float bvb[4] = {bb.x, bb.y, bb.z, bb.w};
        float pvb[4] = {pp.x, pp.y, pp.z, pp.w};
        #pragma unroll
        for (int ri = 0; ri < 4; ri++)
            #pragma unroll
            for (int cj = 0; cj < 4; cj++) {
                float v = accv[ri][cj] + bvb[cj];
                v = (v >= 0.f) ? v : pvb[cj] * v;
                sU[(cg + cj) * 72 + rg + ri]  = v;
                sUh[(rg + ri) * 72 + cg + cj] = __float2half_rn(v);
            }
    }
    __syncthreads();

    // att dots from fp32 sU
    {
        const int r = tid >> 2, h = tid & 3;
        float sa = 0.f, da = 0.f;
        #pragma unroll 8
        for (int k = 0; k < 64; k++) {
            float uv = sU[k * 72 + r];
            sa += uv * sC [h * 68 + k];
            da += uv * sC2[h * 68 + k];
        }
        int gr = row0 + r;
        if (gr < nrows) {
            g_asrc[gr * 4 + h] = sa;
            g_adst[gr * 4 + h] = da;
        }
    }

    // coalesced fp16 u store
    for (int i = tid; i < 512; i += 256) {
        int r = i >> 3, q = i & 7;
        int gr = row0 + r;
        if (gr < nrows)
            *(uint4*)(g_uh + (size_t)gr * 64 + q * 8) =
                *(const uint4*)(sUh + r * 72 + q * 8);
    }
}

// ============================================================================
// K_scan: single-pass decoupled chained scan over g_cnt -> rowptr/cursor.
// Ticket assignment guarantees forward progress; flags via atomics (L2).
// ============================================================================
__global__ __launch_bounds__(512) void k_scan(int n, int e) {
    __shared__ int sh[512];
    __shared__ int bid_s, pref_s;
    if (threadIdx.x == 0) bid_s = atomicAdd(&g_ticket, 1);
    __syncthreads();
    const int bid = bid_s;
    int i = bid * 512 + threadIdx.x;
    int v = (i < n) ? g_cnt[i] : 0;
    sh[threadIdx.x] = v;
    __syncthreads();
    #pragma unroll
    for (int off = 1; off < 512; off <<= 1) {
        int t = (threadIdx.x >= off) ? sh[threadIdx.x - off] : 0;
        __syncthreads();
        sh[threadIdx.x] += t;
        __syncthreads();
    }
    if (threadIdx.x == 0) {
        int pref = 0;
        if (bid > 0) {
            while (atomicAdd(&g_sflag[bid - 1], 0) == 0) { }
            pref = atomicAdd(&g_spref[bid - 1], 0);
        }
        pref_s = pref;
        atomicExch(&g_spref[bid], pref + sh[511]);
        __threadfence();
        atomicExch(&g_sflag[bid], 1);
    }
    __syncthreads();
    int pref = pref_s;
    if (i < n) {
        int val = pref + sh[threadIdx.x] - v;
        g_rowptr[i] = val;
        g_cursor[i] = val;
    }
    if (i == 0) g_rowptr[n] = e;
}

// ============================================================================
// K2: fused edge weights + CSR scatter (1 atomic + 20B per edge; no dnm atomics)
// ============================================================================
__global__ __launch_bounds__(256) void k_edgeW(const int* __restrict__ src,
                                               const int* __restrict__ dst,
                                               int n, int e)
{
    int i = blockIdx.x * 256 + threadIdx.x;
    if (i < e) {
        int s = src[i], d = dst[i];
        float4 a = ((const float4*)g_asrc)[s];
        float4 b = ((const float4*)g_adst)[d];
        float4 w = make_float4(fexp(lrelu(a.x + b.x)), fexp(lrelu(a.y + b.y)),
                               fexp(lrelu(a.z + b.z)), fexp(lrelu(a.w + b.w)));
        int pos = atomicAdd(&g_cursor[d], 1);
        g_csrc[pos] = s;
        ((float4*)g_wcsr)[pos] = w;
    } else if (i < e + n) {
        int v = i - e;
        float4 a = ((const float4*)g_asrc)[v];
        float4 b = ((const float4*)g_adst)[v];
        float4 w = make_float4(fexp(lrelu(a.x + b.x)), fexp(lrelu(a.y + b.y)),
                               fexp(lrelu(a.z + b.z)), fexp(lrelu(a.w + b.w)));
        ((float4*)g_wself)[v] = w;
    }
}

// ============================================================================
// K4: warp-per-node gather over u (fp16, 128B/edge); pure broadcast + FMA.
//     Softmax denominators accumulated inline from the same wcsr values.
//     z[n][h*64+2lane..] = (0.25/denom_h) * sum_e w_he * u[src]
// ============================================================================
__global__ __launch_bounds__(256) void k_gather(int n)
{
    int gw = (blockIdx.x * blockDim.x + threadIdx.x) >> 5;
    if (gw >= n) return;
    const int lane = threadIdx.x & 31;

    float4 ws = ((const float4*)g_wself)[gw];
    float s0 = ws.x, s1 = ws.y, s2 = ws.z, s3 = ws.w;
    float2 u = __half22float2(((const __half2*)g_uh)[(size_t)gw * 32 + lane]);
    float2 A0 = make_float2(ws.x * u.x, ws.x * u.y);
    float2 A1 = make_float2(ws.y * u.x, ws.y * u.y);
    float2 A2 = make_float2(ws.z * u.x, ws.z * u.y);
    float2 A3 = make_float2(ws.w * u.x, ws.w * u.y);

    const int eb = g_rowptr[gw], ee = g_rowptr[gw + 1];
    #pragma unroll 4
    for (int e = eb; e < ee; e++) {
        int src  = g_csrc[e];
        float4 w = ((const float4*)g_wcsr)[e];
        float2 v = __half22float2(((const __half2*)g_uh)[(size_t)src * 32 + lane]);
        s0 += w.x; s1 += w.y; s2 += w.z; s3 += w.w;
        A0.x = fmaf(w.x, v.x, A0.x); A0.y = fmaf(w.x, v.y, A0.y);
        A1.x = fmaf(w.y, v.x, A1.x); A1.y = fmaf(w.y, v.y, A1.y);
        A2.x = fmaf(w.z, v.x, A2.x); A2.y = fmaf(w.z, v.y, A2.y);
        A3.x = fmaf(w.w, v.x, A3.x); A3.y = fmaf(w.w, v.y, A3.y);
    }

    float i0 = 0.25f / s0, i1 = 0.25f / s1, i2 = 0.25f / s2, i3 = 0.25f / s3;
    __half2* z = (__half2*)(g_zh + (size_t)gw * 256);
    z[0 * 32 + lane] = __floats2half2_rn(A0.x * i0, A0.y * i0);
    z[1 * 32 + lane] = __floats2half2_rn(A1.x * i1, A1.y * i1);
    z[2 * 32 + lane] = __floats2half2_rn(A2.x * i2, A2.y * i2);
    z[3 * 32 + lane] = __floats2half2_rn(A3.x * i3, A3.y * i3);
}

// ============================================================================
// K5: out = z B^T via wmma fp16 (M=64, N=64, K=256), ldm=264 padding
// ============================================================================
#define KG_SMEM (2 * 64 * 264 * 2)   // two fp16 tiles [64][264]

__global__ __launch_bounds__(256) void k_gemm2(float* __restrict__ out, int nrows)
{
    extern __shared__ __half smh[];
    __half* sZh = smh;                 // [64][264]
    __half* sB  = smh + 64 * 264;      // [64][264]
    const int tid  = threadIdx.x;
    const int row0 = blockIdx.x * 64;
    const int rmax = nrows - row0;

    for (int i = tid; i < 64 * 32; i += 256) {
        int r = i >> 5, q = i & 31;
        uint4 v = make_uint4(0u, 0u, 0u, 0u);
        if (r < rmax) v = *(const uint4*)(g_zh + (size_t)(row0 + r) * 256 + q * 8);
        *(uint4*)(sZh + r * 264 + q * 8) = v;
    }
    for (int i = tid; i < 64 * 32; i += 256) {
        int r = i >> 5, q = i & 31;
        *(uint4*)(sB + r * 264 + q * 8) = *(const uint4*)(g_wgT + r * 256 + q * 8);
    }
    __syncthreads();

    const int wid = tid >> 5;
    const int mg  = wid >> 1;          // m tile 0..3
    const int ng  = (wid & 1) * 2;     // n tiles ng, ng+1

    wmma::fragment<wmma::accumulator, 16, 16, 16, float> acc[2];
    wmma::fill_fragment(acc[0], 0.0f);
    wmma::fill_fragment(acc[1], 0.0f);

    #pragma unroll
    for (int ks = 0; ks < 16; ks++) {
        wmma::fragment<wmma::matrix_a, 16, 16, 16, __half, wmma::row_major> af;
        wmma::load_matrix_sync(af, sZh + mg * 16 * 264 + ks * 16, 264);
        #pragma unroll
        for (int t = 0; t < 2; t++) {
            wmma::fragment<wmma::matrix_b, 16, 16, 16, __half, wmma::col_major> bf;
            wmma::load_matrix_sync(bf, sB + (ng + t) * 16 * 264 + ks * 16, 264);
            wmma::mma_sync(acc[t], af, bf, acc[t]);
        }
    }

    if (rmax >= 64) {
        #pragma unroll
        for (int t = 0; t < 2; t++)
            wmma::store_matrix_sync(out + (size_t)(row0 + mg * 16) * 64 + (ng + t) * 16,
                                    acc[t], 64, wmma::mem_row_major);
    } else {
        __syncthreads();   // uniform per block: safe
        float* stg = (float*)smh + wid * 320;   // 16 x 20
        const int lane = tid & 31;
        #pragma unroll
        for (int t = 0; t < 2; t++) {
            wmma::store_matrix_sync(stg, acc[t], 20, wmma::mem_row_major);
            __syncwarp();
            for (int j = lane; j < 256; j += 32) {
                int rr = j >> 4, cc = j & 15;
                int node = row0 + mg * 16 + rr;
                if (node < nrows)
                    out[(size_t)node * 64 + (ng + t) * 16 + cc] = stg[rr * 20 + cc];
            }
            __syncwarp();
        }
    }
}

// ============================================================================
// BatchNorm stats + (last block) scale/shift prep; then apply+ReLU.
// gat_bias cancels under batch-stat BN.
// ============================================================================
__global__ void k_bnstats(const float* __restrict__ out,
                          const float* __restrict__ gamma,
                          const float* __restrict__ beta, int nnodes) {
    __shared__ double shs[256], shq[256];
    __shared__ int last_s;
    const int c = threadIdx.x & 63;
    const int g = threadIdx.x >> 6;
    double s = 0.0, q = 0.0;
    for (int r = blockIdx.x * 4 + g; r < nnodes; r += gridDim.x * 4) {
        float v = out[(size_t)r * D + c];
        s += v;
        q += (double)v * v;
    }
    shs[threadIdx.x] = s; shq[threadIdx.x] = q;
    __syncthreads();
    if (g == 0) {
        s = shs[c] + shs[c + 64] + shs[c + 128] + shs[c + 192];
        q = shq[c] + shq[c + 64] + shq[c + 128] + shq[c + 192];
        atomicAdd(&g_sums[c], s);
        atomicAdd(&g_sums[64 + c], q);
    }
    __threadfence();
    __syncthreads();
    if (threadIdx.x == 0)
        last_s = (atomicAdd(&g_bncnt, 1) == (int)gridDim.x - 1);
    __syncthreads();
    if (last_s && threadIdx.x < 64) {
        int cc = threadIdx.x;
        double mean = __ldcg(&g_sums[cc]) / nnodes;
        double var  = __ldcg(&g_sums[64 + cc]) / nnodes - mean * mean;
        float scale = gamma[cc] * rsqrtf((float)var + BN_EPS);
        g_bnsc[cc] = scale;
        g_bnsh[cc] = beta[cc] - (float)mean * scale;
    }
}

__global__ void k_bnfinal(float* __restrict__ out, int nnodes) {
    int i = blockIdx.x * blockDim.x + threadIdx.x;
    int total = nnodes * 16;
    if (i >= total) return;
    int c4 = (i & 15) << 2;
    float4 v = ((float4*)out)[i];
    float4 sc = *(const float4*)(g_bnsc + c4);
    float4 sh = *(const float4*)(g_bnsh + c4);
    v.x = fmaxf(0.f, v.x * sc.x + sh.x);
    v.y = fmaxf(0.f, v.y * sc.y + sh.y);
    v.z = fmaxf(0.f, v.z * sc.z + sh.z);
    v.w = fmaxf(0.f, v.w * sc.w + sh.w);
    ((float4*)out)[i] = v;
}

// ============================================================================
extern "C" void kernel_launch(void* const* d_in, const int* in_sizes, int n_in,
                              void* d_out, int out_size)
{
    const float* x    = (const float*)d_in[0];
    const int*   ei   = (const int*)  d_in[1];
    const float* Wlin = (const float*)d_in[2];
    const float* blin = (const float*)d_in[3];
    const float* pw   = (const float*)d_in[4];
    const float* Wgat = (const float*)d_in[5];
    const float* attS = (const float*)d_in[6];
    const float* attD = (const float*)d_in[7];
    // d_in[8] = gat_bias: cancels under batch-stat BatchNorm.
    const float* gamma = (const float*)d_in[9];
    const float* beta  = (const float*)d_in[10];
    float* out = (float*)d_out;

    int n = in_sizes[0] / D;     // 50000
    int e = in_sizes[1] / 2;     // 800000
    const int* srcA = ei;
    const int* dstA = ei + e;

    static int inited = 0;
    if (!inited) {
        cudaFuncSetAttribute(k_ulinear, cudaFuncAttributeMaxDynamicSharedMemorySize, KA_SMEM);
        cudaFuncSetAttribute(k_gemm2,   cudaFuncAttributeMaxDynamicSharedMemorySize, KG_SMEM);
        inited = 1;
    }

    int nch = (n + 511) / 512;   // 98 <= 256
    int nblk = (n + 63) / 64;

    k_init<<<200, 256>>>(Wgat, attS, attD, n);                               // 0
    k_ulinear<<<nblk, 256, KA_SMEM>>>(x, Wlin, blin, pw, dstA, n, e);        // 1
    k_scan<<<nch, 512>>>(n, e);                                              // 2
    k_edgeW<<<(e + n + 255) / 256, 256>>>(srcA, dstA, n, e);                 // 3
    k_gather<<<(n * 32 + 255) / 256, 256>>>(n);                              // 4
    k_gemm2<<<nblk, 256, KG_SMEM>>>(out, n);                                 // 5
    k_bnstats<<<200, 256>>>(out, gamma, beta, n);                            // 6
    k_bnfinal<<<(n * 16 + 255) / 256, 256>>>(out, n);                        // 7
}

// round 12
// speedup vs baseline: 1.6177x; 1.6177x over previous
#include <cuda_runtime.h>
#include <cuda_fp16.h>
#include <mma.h>
#include <cstdint>
#include <cstddef>

using namespace nvcuda;

#define D   64
#define H   4
#define NEG 0.2f
#define BN_EPS 1e-5f

#define NMAX 50000
#define EMAX 800000

// ---------------- scratch (static device globals; no allocation) ----------------
__device__ __half  g_uh[(size_t)NMAX * 64];     // [N][64] fp16 post-PReLU features
__device__ __half  g_zh[(size_t)NMAX * 256];    // [N][h*64+k] fp16 aggregated u
__device__ __half  g_wgT[64 * 256];             // B[j][h*64+k] = Wgat[(h*64+j)*64+k]
__device__ float  g_asrc[NMAX * H];
__device__ float  g_adst[NMAX * H];
__device__ float  g_wcsr[(size_t)EMAX * H];     // per-edge weights (CSR order)
__device__ float  g_wself[NMAX * H];
__device__ float  g_cs[H * D];                  // W_gat_h^T att_src_h
__device__ float  g_cd[H * D];                  // W_gat_h^T att_dst_h
__device__ int    g_cnt[NMAX];
__device__ int    g_rowptr[NMAX + 1];
__device__ int    g_cursor[NMAX];
__device__ int    g_csrc[EMAX];
__device__ int    g_bsum[256];
__device__ double g_sums[128];                  // [0:64) sum, [64:128) sumsq
__device__ float  g_bnsc[64], g_bnsh[64];

// ---------------- fast exp: FMA polynomial (no MUFU) ----------------
__device__ __forceinline__ float fexp(float x) {
    x = fmaxf(x, -80.f);
    float y  = x * 1.44269504089f;
    float t  = y + 12582912.0f;
    int   ki = __float_as_int(t) - 0x4B400000;
    float r  = y - (t - 12582912.0f);
    float p  = 1.5403530e-4f;
    p = fmaf(p, r, 1.3333558e-3f);
    p = fmaf(p, r, 9.6181291e-3f);
    p = fmaf(p, r, 5.5504109e-2f);
    p = fmaf(p, r, 2.4022651e-1f);
    p = fmaf(p, r, 6.9314718e-1f);
    p = fmaf(p, r, 1.0f);
    return __int_as_float(__float_as_int(p) + (ki << 23));
}

__device__ __forceinline__ float lrelu(float v) { return (v >= 0.f) ? v : NEG * v; }

// ============================================================================
// K_init: zero counters/sums; block 0 builds c_src/c_dst + fp16 B matrix
// ============================================================================
__global__ void k_init(const float* __restrict__ Wgat,
                       const float* __restrict__ attS,
                       const float* __restrict__ attD, int n) {
    int gid = blockIdx.x * blockDim.x + threadIdx.x;
    int stride = gridDim.x * blockDim.x;
    for (int i = gid; i < n; i += stride) g_cnt[i] = 0;
    if (blockIdx.x == 0) {
        int tid = threadIdx.x;
        if (tid < 128) g_sums[tid] = 0.0;
        {
            int h = tid >> 6, k = tid & 63;
            float s = 0.f, d2 = 0.f;
            #pragma unroll 8
            for (int dd = 0; dd < 64; dd++) {
                float wv = Wgat[(h * 64 + dd) * 64 + k];
                s  += attS[h * 64 + dd] * wv;
                d2 += attD[h * 64 + dd] * wv;
            }
            g_cs[tid] = s;
            g_cd[tid] = d2;
        }
        for (int i = tid; i < 64 * 256; i += 256) {
            int j = i >> 8, c = i & 255;
            int h = c >> 6, k = c & 63;
            g_wgT[j * 256 + c] = __float2half_rn(Wgat[(h * 64 + j) * 64 + k]);
        }
    }
}

// ============================================================================
// K_A: u = PReLU(x W_lin^T + b) -> g_uh (fp16);  a_src/a_dst dots;  histogram.
// ============================================================================
#define KA_FLOATS (4608 + 4608 + 2*68*4 + 2304)
#define KA_SMEM   (KA_FLOATS * 4)

__global__ __launch_bounds__(256) void k_ulinear(
    const float* __restrict__ x, const float* __restrict__ Wlin,
    const float* __restrict__ blin, const float* __restrict__ pw,
    const int* __restrict__ dstA, int nrows, int nedges)
{
    extern __shared__ float sm[];
    float*  sX  = sm;                        // [64][72] x tile; later aliased by sU
    float*  sU  = sm;                        // [col][row] u fp32 (alias of sX)
    float*  sW  = sm + 4608;                 // [64][72] Wlin^T
    float*  sC  = sm + 9216;                 // [4][68]
    float*  sC2 = sm + 9216 + 272;           // [4][68]
    __half* sUh = (__half*)(sm + 9760);      // [row][72] u fp16
    const int tid  = threadIdx.x;
    const int row0 = blockIdx.x * 64;

    // destination histogram (independent, overlaps)
    {
        int gid = blockIdx.x * 256 + tid;
        int stride = gridDim.x * 256;
        for (int i = gid; i < nedges; i += stride)
            atomicAdd(&g_cnt[dstA[i]], 1);
    }

    {
        int h = tid >> 6, k = tid & 63;
        sC [h * 68 + k] = g_cs[tid];
        sC2[h * 68 + k] = g_cd[tid];
    }
    for (int i = tid; i < 64 * 64; i += 256) {
        int r = i >> 6, k = i & 63;
        int gr = row0 + r;
        sX[k * 72 + r] = (gr < nrows) ? x[(size_t)gr * D + k] : 0.f;
    }
    for (int i = tid; i < 64 * 64; i += 256) {
        int j = i >> 6, k = i & 63;
        sW[k * 72 + j] = Wlin[i];
    }
    __syncthreads();

    float accv[4][4];
    {
        const int rg = (tid >> 4) << 2;
        const int cg = (tid & 15) << 2;
        #pragma unroll
        for (int a = 0; a < 4; a++)
            #pragma unroll
            for (int b = 0; b < 4; b++) accv[a][b] = 0.f;
        #pragma unroll 8
        for (int k = 0; k < 64; k++) {
            float4 a4 = *(const float4*)(sX + k * 72 + rg);
            float4 b4 = *(const float4*)(sW + k * 72 + cg);
            float av[4] = {a4.x, a4.y, a4.z, a4.w};
            float bv[4] = {b4.x, b4.y, b4.z, b4.w};
            #pragma unroll
            for (int ri = 0; ri < 4; ri++)
                #pragma unroll
                for (int cj = 0; cj < 4; cj++) accv[ri][cj] += av[ri] * bv[cj];
        }
    }
    __syncthreads();   // all reads of sX done; safe to alias with sU

    {
        const int rg = (tid >> 4) << 2;
        const int cg = (tid & 15) << 2;
        float4 bb = *(const float4*)(blin + cg);
        float4 pp = *(const float4*)(pw + cg);
        float bvb[4] = {bb.x, bb.y, bb.z, bb.w};
        float pvb[4] = {pp.x, pp.y, pp.z, pp.w};
        #pragma unroll
        for (int ri = 0; ri < 4; ri++)
            #pragma unroll
            for (int cj = 0; cj < 4; cj++) {
                float v = accv[ri][cj] + bvb[cj];
                v = (v >= 0.f) ? v : pvb[cj] * v;
                sU[(cg + cj) * 72 + rg + ri]  = v;
                sUh[(rg + ri) * 72 + cg + cj] = __float2half_rn(v);
            }
    }
    __syncthreads();

    // att dots from fp32 sU
    {
        const int r = tid >> 2, h = tid & 3;
        float sa = 0.f, da = 0.f;
        #pragma unroll 8
        for (int k = 0; k < 64; k++) {
            float uv = sU[k * 72 + r];
            sa += uv * sC [h * 68 + k];
            da += uv * sC2[h * 68 + k];
        }
        int gr = row0 + r;
        if (gr < nrows) {
            g_asrc[gr * 4 + h] = sa;
            g_adst[gr * 4 + h] = da;
        }
    }

    // coalesced fp16 u store
    for (int i = tid; i < 512; i += 256) {
        int r = i >> 3, q = i & 7;
        int gr = row0 + r;
        if (gr < nrows)
            *(uint4*)(g_uh + (size_t)gr * 64 + q * 8) =
                *(const uint4*)(sUh + r * 72 + q * 8);
    }
}

// ============================================================================
// scan (3 small kernels — known good)
// ============================================================================
__global__ void k_scanA(int n) {
    __shared__ int sh[512];
    int i = blockIdx.x * 512 + threadIdx.x;
    int v = (i < n) ? g_cnt[i] : 0;
    sh[threadIdx.x] = v;
    __syncthreads();
    #pragma unroll
    for (int off = 1; off < 512; off <<= 1) {
        int t = (threadIdx.x >= off) ? sh[threadIdx.x - off] : 0;
        __syncthreads();
        sh[threadIdx.x] += t;
        __syncthreads();
    }
    if (i < n) g_rowptr[i] = sh[threadIdx.x] - v;
    if (threadIdx.x == 511) g_bsum[blockIdx.x] = sh[511];
}

__global__ void k_scanB(int nch) {
    __shared__ int sh[256];
    int v = (threadIdx.x < nch) ? g_bsum[threadIdx.x] : 0;
    sh[threadIdx.x] = v;
    __syncthreads();
    #pragma unroll
    for (int off = 1; off < 256; off <<= 1) {
        int t = (threadIdx.x >= off) ? sh[threadIdx.x - off] : 0;
        __syncthreads();
        sh[threadIdx.x] += t;
        __syncthreads();
    }
    if (threadIdx.x < nch) g_bsum[threadIdx.x] = sh[threadIdx.x] - v;
}

__global__ void k_scanC(int n, int e) {
    int i = blockIdx.x * blockDim.x + threadIdx.x;
    if (i < n) {
        int v = g_rowptr[i] + g_bsum[i >> 9];
        g_rowptr[i] = v;
        g_cursor[i] = v;
    }
    if (i == 0) g_rowptr[n] = e;
}

// ============================================================================
// K2: fused edge weights + CSR scatter (1 atomic + 20B per edge; NO dnm atomics)
// ============================================================================
__global__ __launch_bounds__(256) void k_edgeW(const int* __restrict__ src,
                                               const int* __restrict__ dst,
                                               int n, int e)
{
    int i = blockIdx.x * 256 + threadIdx.x;
    if (i < e) {
        int s = src[i], d = dst[i];
        float4 a = ((const float4*)g_asrc)[s];
        float4 b = ((const float4*)g_adst)[d];
        float4 w = make_float4(fexp(lrelu(a.x + b.x)), fexp(lrelu(a.y + b.y)),
                               fexp(lrelu(a.z + b.z)), fexp(lrelu(a.w + b.w)));
        int pos = atomicAdd(&g_cursor[d], 1);
        g_csrc[pos] = s;
        ((float4*)g_wcsr)[pos] = w;
    } else if (i < e + n) {
        int v = i - e;
        float4 a = ((const float4*)g_asrc)[v];
        float4 b = ((const float4*)g_adst)[v];
        float4 w = make_float4(fexp(lrelu(a.x + b.x)), fexp(lrelu(a.y + b.y)),
                               fexp(lrelu(a.z + b.z)), fexp(lrelu(a.w + b.w)));
        ((float4*)g_wself)[v] = w;
    }
}

// ============================================================================
// K4: warp-per-node gather over u (fp16, 128B/edge); pure broadcast + FMA.
//     Softmax denominators accumulated inline from the same wcsr float4.
//     z[n][h*64+2lane..] = (0.25/denom_h) * sum_e w_he * u[src]
// ============================================================================
__global__ __launch_bounds__(256) void k_gather(int n)
{
    int gw = (blockIdx.x * blockDim.x + threadIdx.x) >> 5;
    if (gw >= n) return;
    const int lane = threadIdx.x & 31;

    float4 ws = ((const float4*)g_wself)[gw];
    float s0 = ws.x, s1 = ws.y, s2 = ws.z, s3 = ws.w;
    float2 u = __half22float2(((const __half2*)g_uh)[(size_t)gw * 32 + lane]);
    float2 A0 = make_float2(ws.x * u.x, ws.x * u.y);
    float2 A1 = make_float2(ws.y * u.x, ws.y * u.y);
    float2 A2 = make_float2(ws.z * u.x, ws.z * u.y);
    float2 A3 = make_float2(ws.w * u.x, ws.w * u.y);

    const int eb = g_rowptr[gw], ee = g_rowptr[gw + 1];
    #pragma unroll 4
    for (int e = eb; e < ee; e++) {
        int src  = g_csrc[e];
        float4 w = ((const float4*)g_wcsr)[e];
        float2 v = __half22float2(((const __half2*)g_uh)[(size_t)src * 32 + lane]);
        s0 += w.x; s1 += w.y; s2 += w.z; s3 += w.w;
        A0.x = fmaf(w.x, v.x, A0.x); A0.y = fmaf(w.x, v.y, A0.y);
        A1.x = fmaf(w.y, v.x, A1.x); A1.y = fmaf(w.y, v.y, A1.y);
        A2.x = fmaf(w.z, v.x, A2.x); A2.y = fmaf(w.z, v.y, A2.y);
        A3.x = fmaf(w.w, v.x, A3.x); A3.y = fmaf(w.w, v.y, A3.y);
    }

    float i0 = 0.25f / s0, i1 = 0.25f / s1, i2 = 0.25f / s2, i3 = 0.25f / s3;
    __half2* z = (__half2*)(g_zh + (size_t)gw * 256);
    z[0 * 32 + lane] = __floats2half2_rn(A0.x * i0, A0.y * i0);
    z[1 * 32 + lane] = __floats2half2_rn(A1.x * i1, A1.y * i1);
    z[2 * 32 + lane] = __floats2half2_rn(A2.x * i2, A2.y * i2);
    z[3 * 32 + lane] = __floats2half2_rn(A3.x * i3, A3.y * i3);
}

// ============================================================================
// K5: out = z B^T via wmma fp16 (M=64, N=64, K=256), ldm=264 padding
// ============================================================================
#define KG_SMEM (2 * 64 * 264 * 2)   // two fp16 tiles [64][264]

__global__ __launch_bounds__(256) void k_gemm2(float* __restrict__ out, int nrows)
{
    extern __shared__ __half smh[];
    __half* sZh = smh;                 // [64][264]
    __half* sB  = smh + 64 * 264;      // [64][264]
    const int tid  = threadIdx.x;
    const int row0 = blockIdx.x * 64;
    const int rmax = nrows - row0;

    for (int i = tid; i < 64 * 32; i += 256) {
        int r = i >> 5, q = i & 31;
        uint4 v = make_uint4(0u, 0u, 0u, 0u);
        if (r < rmax) v = *(const uint4*)(g_zh + (size_t)(row0 + r) * 256 + q * 8);
        *(uint4*)(sZh + r * 264 + q * 8) = v;
    }
    for (int i = tid; i < 64 * 32; i += 256) {
        int r = i >> 5, q = i & 31;
        *(uint4*)(sB + r * 264 + q * 8) = *(const uint4*)(g_wgT + r * 256 + q * 8);
    }
    __syncthreads();

    const int wid = tid >> 5;
    const int mg  = wid >> 1;          // m tile 0..3
    const int ng  = (wid & 1) * 2;     // n tiles ng, ng+1

    wmma::fragment<wmma::accumulator, 16, 16, 16, float> acc[2];
    wmma::fill_fragment(acc[0], 0.0f);
    wmma::fill_fragment(acc[1], 0.0f);

    #pragma unroll
    for (int ks = 0; ks < 16; ks++) {
        wmma::fragment<wmma::matrix_a, 16, 16, 16, __half, wmma::row_major> af;
        wmma::load_matrix_sync(af, sZh + mg * 16 * 264 + ks * 16, 264);
        #pragma unroll
        for (int t = 0; t < 2; t++) {
            wmma::fragment<wmma::matrix_b, 16, 16, 16, __half, wmma::col_major> bf;
            wmma::load_matrix_sync(bf, sB + (ng + t) * 16 * 264 + ks * 16, 264);
            wmma::mma_sync(acc[t], af, bf, acc[t]);
        }
    }

    if (rmax >= 64) {
        #pragma unroll
        for (int t = 0; t < 2; t++)
            wmma::store_matrix_sync(out + (size_t)(row0 + mg * 16) * 64 + (ng + t) * 16,
                                    acc[t], 64, wmma::mem_row_major);
    } else {
        __syncthreads();   // uniform per block: safe
        float* stg = (float*)smh + wid * 320;   // 16 x 20
        const int lane = tid & 31;
        #pragma unroll
        for (int t = 0; t < 2; t++) {
            wmma::store_matrix_sync(stg, acc[t], 20, wmma::mem_row_major);
            __syncwarp();
            for (int j = lane; j < 256; j += 32) {
                int rr = j >> 4, cc = j & 15;
                int node = row0 + mg * 16 + rr;
                if (node < nrows)
                    out[(size_t)node * 64 + (ng + t) * 16 + cc] = stg[rr * 20 + cc];
            }
            __syncwarp();
        }
    }
}

// ============================================================================
// BatchNorm (batch stats; gat_bias cancels) + ReLU — separate kernels (known good)
// ============================================================================
__global__ void k_bnstats(const float* __restrict__ out, int nnodes) {
    __shared__ double shs[256], shq[256];
    const int c = threadIdx.x & 63;
    const int g = threadIdx.x >> 6;
    double s = 0.0, q = 0.0;
    for (int r = blockIdx.x * 4 + g; r < nnodes; r += gridDim.x * 4) {
        float v = out[(size_t)r * D + c];
        s += v;
        q += (double)v * v;
    }
    shs[threadIdx.x] = s; shq[threadIdx.x] = q;
    __syncthreads();
    if (g == 0) {
        s = shs[c] + shs[c + 64] + shs[c + 128] + shs[c + 192];
        q = shq[c] + shq[c + 64] + shq[c + 128] + shq[c + 192];
        atomicAdd(&g_sums[c], s);
        atomicAdd(&g_sums[64 + c], q);
    }
}

__global__ void k_bnprep(const float* __restrict__ gamma,
                         const float* __restrict__ beta, int nnodes) {
    int c = threadIdx.x;
    if (c < 64) {
        double mean = g_sums[c] / nnodes;
        double var  = g_sums[64 + c] / nnodes - mean * mean;
        float scale = gamma[c] * rsqrtf((float)var + BN_EPS);
        g_bnsc[c] = scale;
        g_bnsh[c] = beta[c] - (float)mean * scale;
    }
}

__global__ void k_bnfinal(float* __restrict__ out, int nnodes) {
    int i = blockIdx.x * blockDim.x + threadIdx.x;
    int total = nnodes * 16;
    if (i >= total) return;
    int c4 = (i & 15) << 2;
    float4 v = ((float4*)out)[i];
    float4 sc = *(const float4*)(g_bnsc + c4);
    float4 sh = *(const float4*)(g_bnsh + c4);
    v.x = fmaxf(0.f, v.x * sc.x + sh.x);
    v.y = fmaxf(0.f, v.y * sc.y + sh.y);
    v.z = fmaxf(0.f, v.z * sc.z + sh.z);
    v.w = fmaxf(0.f, v.w * sc.w + sh.w);
    ((float4*)out)[i] = v;
}

// ============================================================================
extern "C" void kernel_launch(void* const* d_in, const int* in_sizes, int n_in,
                              void* d_out, int out_size)
{
    const float* x    = (const float*)d_in[0];
    const int*   ei   = (const int*)  d_in[1];
    const float* Wlin = (const float*)d_in[2];
    const float* blin = (const float*)d_in[3];
    const float* pw   = (const float*)d_in[4];
    const float* Wgat = (const float*)d_in[5];
    const float* attS = (const float*)d_in[6];
    const float* attD = (const float*)d_in[7];
    // d_in[8] = gat_bias: cancels under batch-stat BatchNorm.
    const float* gamma = (const float*)d_in[9];
    const float* beta  = (const float*)d_in[10];
    float* out = (float*)d_out;

    int n = in_sizes[0] / D;     // 50000
    int e = in_sizes[1] / 2;     // 800000
    const int* srcA = ei;
    const int* dstA = ei + e;

    static int inited = 0;
    if (!inited) {
        cudaFuncSetAttribute(k_ulinear, cudaFuncAttributeMaxDynamicSharedMemorySize, KA_SMEM);
        cudaFuncSetAttribute(k_gemm2,   cudaFuncAttributeMaxDynamicSharedMemorySize, KG_SMEM);
        inited = 1;
    }

    int nch = (n + 511) / 512;
    int nblk = (n + 63) / 64;

    k_init<<<200, 256>>>(Wgat, attS, attD, n);                               // 0
    k_ulinear<<<nblk, 256, KA_SMEM>>>(x, Wlin, blin, pw, dstA, n, e);        // 1
    k_scanA<<<nch, 512>>>(n);                                                // 2
    k_scanB<<<1, 256>>>(nch);                                                // 3
    k_scanC<<<(n + 255) / 256, 256>>>(n, e);                                 // 4
    k_edgeW<<<(e + n + 255) / 256, 256>>>(srcA, dstA, n, e);                 // 5
    k_gather<<<(n * 32 + 255) / 256, 256>>>(n);                              // 6
    k_gemm2<<<nblk, 256, KG_SMEM>>>(out, n);                                 // 7
    k_bnstats<<<200, 256>>>(out, n);                                         // 8
    k_bnprep<<<1, 64>>>(gamma, beta, n);                                     // 9
    k_bnfinal<<<(n * 16 + 255) / 256, 256>>>(out, n);                        // 10
}